// round 15
// baseline (speedup 1.0000x reference)
#include <cuda_runtime.h>

#define SEQ   4096
#define CIN   7
#define NUMK  74
#define KH    8
#define KW    3
#define D     1536
#define TLEN  (SEQ * KW)   // 12288
#define NBLK  444          // one block per resident slot (148 SMs x 3): perfectly balanced
#define SPER  10           // max rows per block (blocks own 9 or 10 rows)
#define NH    (3 * SPER)   // 30 conv h-values per block
#define NT    384          // threads per block
#define WLEN  (3 * SPER + 7)  // 37 window values per channel
#define WPAD  40

// ---- packed f32x2 helpers (sm_100a) ----
typedef unsigned long long u64;
#define F2PACK(d, lo, hi)   asm("mov.b64 %0, {%1, %2};"      : "=l"(d) : "f"(lo), "f"(hi))
#define F2UNPACK(lo, hi, s) asm("mov.b64 {%0, %1}, %2;"      : "=f"(lo), "=f"(hi) : "l"(s))
#define F2MUL(d, a, b)      asm("mul.rn.f32x2 %0, %1, %2;"   : "=l"(d) : "l"(a), "l"(b))
#define F2ADD(d, a, b)      asm("add.rn.f32x2 %0, %1, %2;"   : "=l"(d) : "l"(a), "l"(b))
#define F2FMA(d, a, b, c)   asm("fma.rn.f32x2 %0, %1, %2, %3;" : "=l"(d) : "l"(a), "l"(b), "l"(c))

// dynamic smem layout (floats):
#define SM_CONV   0                              // [NH][512] = 15360
#define SM_WCS    (SM_CONV + NH * 512)           // [KH][76]  = 608
#define SM_SXA    (SM_WCS + KH * 76)             // [CIN][40] = 280
#define SM_SXB    (SM_SXA + CIN * WPAD)          // [CIN][40] = 280
#define SM_M      (SM_SXB + CIN * WPAD)          // [SPER][16]= 160 (duplicated pairs; broadcast reads)
#define SMEM_BYTES ((SM_M + SPER * 16) * 4)

// packed-pair conv for one column: h in [hr, hr+2*nsteps), results to convS[h][g]
// dual staggered window copies make every (v_j, v_{j+1}) pair one aligned LDS.64
__device__ __forceinline__ void conv_col(
    const float* __restrict__ sxa,    // copyA: v[i]
    const float* __restrict__ sxb,    // copyB: v[i+1] at index i
    const float* __restrict__ wcsS,   // [k][76]
    int o, int g, int hr, int nsteps, // hr even
    float* __restrict__ convS)
{
    u64 wp[8];
#pragma unroll
    for (int k = 0; k < 8; k++) {
        float w = wcsS[k * 76 + o];
        F2PACK(wp[k], w, w);
    }
    // ring: P[j] = (v[hr+j], v[hr+j+1]);  even j from copyA, odd j from copyB
    u64 P[8];
#pragma unroll
    for (int j = 0; j < 8; j++) {
        P[j] = (j & 1) ? *(const u64*)(sxb + hr + j - 1)
                       : *(const u64*)(sxa + hr + j);
    }

#pragma unroll
    for (int t = 0; t < nsteps; t++) {
        const int h = hr + 2 * t;
        u64 acc;
        F2MUL(acc, wp[0], P[(2 * t) & 7]);
#pragma unroll
        for (int k = 1; k < 8; k++)
            F2FMA(acc, wp[k], P[(2 * t + k) & 7], acc);
        float lo, hi;
        F2UNPACK(lo, hi, acc);
        convS[h * 512 + g]       = lo;
        convS[(h + 1) * 512 + g] = hi;
        if (t < nsteps - 1) {
            P[(2 * t) & 7]     = *(const u64*)(sxa + hr + 2 * t + 8);
            P[(2 * t + 1) & 7] = *(const u64*)(sxb + hr + 2 * t + 8);
        }
    }
}

// ---------------- single kernel: conv to smem, then tables-by-rotation ----------------
__global__ __launch_bounds__(NT, 3) void embed_kernel(
    const float* __restrict__ x,       // (4096, 7)
    const float* __restrict__ kern,    // (74, 8, 3)
    const int*   __restrict__ xm,      // (4096, 4)
    float*       __restrict__ out)     // (4096, 1536)
{
    extern __shared__ float smem[];
    float* __restrict__ convS = smem + SM_CONV;
    float* __restrict__ wcsS  = smem + SM_WCS;
    float* __restrict__ sxA   = smem + SM_SXA;
    float* __restrict__ sxB   = smem + SM_SXB;
    float* __restrict__ mS    = smem + SM_M;

    // balanced partition: block b owns rows [b*SEQ/NBLK, (b+1)*SEQ/NBLK)  -> 9 or 10 rows
    const int b    = blockIdx.x;
    const int s0   = (b * SEQ) / NBLK;
    const int rmax = ((b + 1) * SEQ) / NBLK - s0;
    const int tid  = threadIdx.x;

    // ---- stage weights: wc[o][k] = kern[o*24 + k*3 + 1]
    for (int e = tid; e < NUMK * KH; e += NT) {
        int o = e / KH, k = e - o * KH;
        wcsS[k * 76 + o] = kern[o * (KH * KW) + k * KW + 1];
    }
    // ---- stage x window (dual staggered copies): i in [0, WLEN), t = 3*s0 - 4 + i
    if (tid < CIN * WLEN) {
        int c = tid / WLEN, i = tid - c * WLEN;
        int t = 3 * s0 - 4 + i;
        float v = 0.0f;
        if (t >= 0 && t < TLEN) {
            int row = t / 3 + t % 3;
            if (row > SEQ - 1) row = SEQ - 1;
            v = x[row * CIN + c];
        }
        sxA[c * WPAD + i] = v;
        if (i > 0) sxB[c * WPAD + i - 1] = v;
    }
    // ---- stage duplicated temporal multiplicity pairs:
    //      mS[r][2a, 2a+1] = (a==0 ? 0 : m, m) where m = #{k : xm[s][k]==a}
    if (tid >= 288 && tid < 288 + SPER * 7) {
        int e = tid - 288;
        int r = e / 7, a = e - r * 7;
        int s = s0 + r; if (s > SEQ - 1) s = SEQ - 1;   // clamp (stores predicated off anyway)
        const int* xr = xm + s * 4;
        float m = (float)((xr[0] == a) + (xr[1] == a) + (xr[2] == a) + (xr[3] == a));
        mS[r * 16 + 2 * a]     = (a == 0) ? 0.0f : m;
        mS[r * 16 + 2 * a + 1] = m;
        if (a == 6) { mS[r * 16 + 14] = m; mS[r * 16 + 15] = m; }  // a=6 real; pad slot 7 = 0
        if (a == 0) { mS[r * 16 + 14] = 0.0f; mS[r * 16 + 15] = 0.0f; } // pad pair (m7) = 0
    }
    __syncthreads();

    // =========== Phase 1 (balanced, fixed 30 h): full column g = tid; plus a 10-h chunk ==========
    {
        const int g = tid;                       // 0..383 -> c <= 5, never 511
        const int c = g / 73, o = g - c * 73;
        conv_col(sxA + c * WPAD, sxB + c * WPAD, wcsS, o, g, 0, NH / 2, convS);
    }
    {
        const int g  = 384 + (tid & 127);        // 384..511
        const int hr = (tid >> 7) * SPER;        // 0, 10, 20 (even)
        int c, o;
        if (g == 511) { c = 0; o = NUMK - 1; }
        else          { c = g / 73; o = g - c * 73; }
        conv_col(sxA + c * WPAD, sxB + c * WPAD, wcsS, o, g, hr, SPER / 2, convS);
    }
    __syncthreads();

    // =========== Phase 2: one float4 column per thread; pe + temporal by rotation ==========
    const int lane = tid & 127;          // 0..127
    const int jj   = tid >> 7;           // 0..2
    const int g0   = 4 * lane;
    const int f    = jj * 512 + g0;      // even; dims f..f+3 = pairs (i0, i0+1)

    const float cexp = (float)(-9.210340371976184 / 1536.0); // -ln(10000)/d
    const float div0 = expf((float)(f) * cexp);
    const float div1 = div0 * 0.988078993f;                  // * 10000^(-2/1536)

    // pe(s0) seed: same float angle as reference, reduced mod 2pi in double, fast sincos
    float ps0, pc0, ps1, pc1;
    {
        const float  pf0 = (float)s0 * div0;
        const float  pf1 = (float)s0 * div1;
        const double twopi  = 6.283185307179586;
        const double inv2pi = 0.15915494309189535;
        float th0 = (float)((double)pf0 - twopi * floor((double)pf0 * inv2pi));
        float th1 = (float)((double)pf1 - twopi * floor((double)pf1 * inv2pi));
        __sincosf(th0, &ps0, &pc0);
        __sincosf(th1, &ps1, &pc1);
    }
    // per-row rotation step: args <= 1 rad -> fast path
    float gs0, gc0, gs1, gc1;
    __sincosf(div0, &gs0, &gc0);
    __sincosf(div1, &gs1, &gc1);

    // packed temporal basis Tp[a] = (sin(a*div), cos(a*div)), a = 1..6
    u64 Tp0[7], Tp1[7];
    F2PACK(Tp0[1], gs0, gc0);
    F2PACK(Tp1[1], gs1, gc1);
    {
        float ts0 = gs0, tc0 = gc0, ts1 = gs1, tc1 = gc1;
#pragma unroll
        for (int a = 2; a <= 6; a++) {
            float ns0 = ts0 * gc0 + tc0 * gs0;
            float nc0 = tc0 * gc0 - ts0 * gs0;
            float ns1 = ts1 * gc1 + tc1 * gs1;
            float nc1 = tc1 * gc1 - ts1 * gs1;
            ts0 = ns0; tc0 = nc0; ts1 = ns1; tc1 = nc1;
            F2PACK(Tp0[a], ts0, tc0);
            F2PACK(Tp1[a], ts1, tc1);
        }
    }

    // packed pe state
    u64 pp0, pp1;
    F2PACK(pp0, ps0, pc0);
    F2PACK(pp1, ps1, pc1);

    float* __restrict__ outp = out + (size_t)s0 * D + f;
    const float* __restrict__ cvp = convS + jj * 512 + g0;   // +1536 per row

#pragma unroll
    for (int r = 0; r < SPER; r++) {
        // 4x LDS.128 (warp-uniform -> broadcast): 8 packed pairs
        const ulonglong2* __restrict__ mp2 = (const ulonglong2*)(mS + r * 16);
        const ulonglong2 ma = mp2[0], mb = mp2[1], mc = mp2[2], md = mp2[3];
        const ulonglong2 cv2 = *(const ulonglong2*)(cvp + r * 3 * 512);

        // seed: (0, m0) + (pe_sin, pe_cos)  — a=0 term and pe folded in one packed add
        u64 t0, t1;
        F2ADD(t0, ma.x, pp0);
        F2ADD(t1, ma.x, pp1);
        F2FMA(t0, ma.y, Tp0[1], t0);  F2FMA(t1, ma.y, Tp1[1], t1);
        F2FMA(t0, mb.x, Tp0[2], t0);  F2FMA(t1, mb.x, Tp1[2], t1);
        F2FMA(t0, mb.y, Tp0[3], t0);  F2FMA(t1, mb.y, Tp1[3], t1);
        F2FMA(t0, mc.x, Tp0[4], t0);  F2FMA(t1, mc.x, Tp1[4], t1);
        F2FMA(t0, mc.y, Tp0[5], t0);  F2FMA(t1, mc.y, Tp1[5], t1);
        F2FMA(t0, md.x, Tp0[6], t0);  F2FMA(t1, md.x, Tp1[6], t1);

        ulonglong2 res;
        F2ADD(res.x, cv2.x, t0);
        F2ADD(res.y, cv2.y, t1);
        if (r < rmax)
            *(ulonglong2*)outp = res;

        // rotate pe (scalar chain), repack
        float ns0 = ps0 * gc0 + pc0 * gs0;
        float nc0 = pc0 * gc0 - ps0 * gs0;
        float ns1 = ps1 * gc1 + pc1 * gs1;
        float nc1 = pc1 * gc1 - ps1 * gs1;
        ps0 = ns0; pc0 = nc0; ps1 = ns1; pc1 = nc1;
        F2PACK(pp0, ps0, pc0);
        F2PACK(pp1, ps1, pc1);

        outp += D;
    }
}

// ---------------- launch ----------------
extern "C" void kernel_launch(void* const* d_in, const int* in_sizes, int n_in,
                              void* d_out, int out_size)
{
    const float* x     = nullptr;
    const float* kern  = nullptr;
    const int*   xmark = nullptr;
    for (int i = 0; i < n_in; i++) {
        if      (in_sizes[i] == SEQ * CIN)        x     = (const float*)d_in[i];
        else if (in_sizes[i] == NUMK * KH * KW)   kern  = (const float*)d_in[i];
        else if (in_sizes[i] == SEQ * 4)          xmark = (const int*)d_in[i];
    }

    cudaFuncSetAttribute(embed_kernel,
                         cudaFuncAttributeMaxDynamicSharedMemorySize, SMEM_BYTES);

    embed_kernel<<<NBLK, NT, SMEM_BYTES>>>(x, kern, xmark, (float*)d_out);
}

// round 16
// speedup vs baseline: 1.0415x; 1.0415x over previous
#include <cuda_runtime.h>

#define SEQ   4096
#define CIN   7
#define NUMK  74
#define KH    8
#define KW    3
#define D     1536
#define TLEN  (SEQ * KW)   // 12288
#define NBLK  444          // one block per resident slot (148 SMs x 3): perfectly balanced
#define SPER  10           // max rows per block (blocks own 9 or 10 rows)
#define NH    (3 * SPER)   // 30 conv h-values (max)
#define NT    384          // threads per block
#define WLEN  (3 * SPER + 7)  // 37 window values per channel
#define WPAD  40

// ---- packed f32x2 helpers (sm_100a) ----
typedef unsigned long long u64;
#define F2PACK(d, lo, hi)   asm("mov.b64 %0, {%1, %2};"      : "=l"(d) : "f"(lo), "f"(hi))
#define F2UNPACK(lo, hi, s) asm("mov.b64 {%0, %1}, %2;"      : "=f"(lo), "=f"(hi) : "l"(s))
#define F2MUL(d, a, b)      asm("mul.rn.f32x2 %0, %1, %2;"   : "=l"(d) : "l"(a), "l"(b))
#define F2ADD(d, a, b)      asm("add.rn.f32x2 %0, %1, %2;"   : "=l"(d) : "l"(a), "l"(b))
#define F2FMA(d, a, b, c)   asm("fma.rn.f32x2 %0, %1, %2, %3;" : "=l"(d) : "l"(a), "l"(b), "l"(c))

// dynamic smem layout (float offsets):
#define SM_CONV   0                              // [NH][512]      = 15360 floats
#define SM_WCSD   (SM_CONV + NH * 512)           // u64[KH][76]    = 1216 floats
#define SM_SXA    (SM_WCSD + KH * 76 * 2)        // [CIN][WPAD]    = 280
#define SM_SXB    (SM_SXA + CIN * WPAD)          // [CIN][WPAD]    = 280
#define SM_M      (SM_SXB + CIN * WPAD)          // [SPER][16]     = 160 (duplicated pairs)
#define SMEM_BYTES ((SM_M + SPER * 16) * 4)

// packed-pair conv for one column: h in [hr, hr+2*NSTEPS), results to convS[h][g]
// dual staggered window copies make every (v_j, v_{j+1}) pair one aligned LDS.64;
// weights come pre-duplicated as (w,w) u64 pairs.
template<int NSTEPS>
__device__ __forceinline__ void conv_col(
    const float* __restrict__ sxa,    // copyA: v[i]
    const float* __restrict__ sxb,    // copyB: v[i+1] at index i
    const u64*   __restrict__ wcsD,   // [k][76] duplicated pairs
    int o, int g, int hr,             // hr even
    float* __restrict__ convS)
{
    u64 wp[8];
#pragma unroll
    for (int k = 0; k < 8; k++)
        wp[k] = wcsD[k * 76 + o];
    // ring: P[j] = (v[hr+j], v[hr+j+1]);  even j from copyA, odd j from copyB
    u64 P[8];
#pragma unroll
    for (int j = 0; j < 8; j++) {
        P[j] = (j & 1) ? *(const u64*)(sxb + hr + j - 1)
                       : *(const u64*)(sxa + hr + j);
    }

#pragma unroll
    for (int t = 0; t < NSTEPS; t++) {
        const int h = hr + 2 * t;
        u64 acc;
        F2MUL(acc, wp[0], P[(2 * t) & 7]);
#pragma unroll
        for (int k = 1; k < 8; k++)
            F2FMA(acc, wp[k], P[(2 * t + k) & 7], acc);
        float lo, hi;
        F2UNPACK(lo, hi, acc);
        convS[h * 512 + g]       = lo;
        convS[(h + 1) * 512 + g] = hi;
        if (t < NSTEPS - 1) {
            P[(2 * t) & 7]     = *(const u64*)(sxa + hr + 2 * t + 8);
            P[(2 * t + 1) & 7] = *(const u64*)(sxb + hr + 2 * t + 8);
        }
    }
}

// templated compute body: phase 1 + phase 2, exact work for RMAX rows
template<int RMAX>
__device__ __forceinline__ void compute_phases(
    float* __restrict__ convS, const u64* __restrict__ wcsD,
    const float* __restrict__ sxA, const float* __restrict__ sxB,
    const float* __restrict__ mS,
    int s0, int tid, float* __restrict__ out)
{
    constexpr int FULL_STEPS = (3 * RMAX + 1) / 2;       // 15 or 14
    constexpr int CH2_STEPS  = FULL_STEPS - 10;          // 5 or 4 (jj==2 chunk)
    const int jj = tid >> 7;             // 0..2

    // ---- Phase 1: full column g = tid; plus a chunk of cols 384..511
    {
        const int g = tid;                       // 0..383 -> c <= 5, never 511
        const int c = g / 73, o = g - c * 73;
        conv_col<FULL_STEPS>(sxA + c * WPAD, sxB + c * WPAD, wcsD, o, g, 0, convS);
    }
    {
        const int g  = 384 + (tid & 127);        // 384..511
        const int hr = jj * 10;                  // 0, 10, 20 (even)
        int c, o;
        if (g == 511) { c = 0; o = NUMK - 1; }
        else          { c = g / 73; o = g - c * 73; }
        if (jj == 2) conv_col<CH2_STEPS>(sxA + c * WPAD, sxB + c * WPAD, wcsD, o, g, hr, convS);
        else         conv_col<5>(sxA + c * WPAD, sxB + c * WPAD, wcsD, o, g, hr, convS);
    }
    __syncthreads();

    // ---- Phase 2: one float4 column per thread; pe + temporal by rotation
    const int lane = tid & 127;
    const int g0   = 4 * lane;
    const int f    = jj * 512 + g0;      // even; dims f..f+3 = pairs (i0, i0+1)

    const float cexp = (float)(-9.210340371976184 / 1536.0); // -ln(10000)/d
    const float div0 = expf((float)(f) * cexp);
    const float div1 = div0 * 0.988078993f;                  // * 10000^(-2/1536)

    // pe(s0) seed: same float angle as reference, reduced mod 2pi in double, fast sincos
    float ps0, pc0, ps1, pc1;
    {
        const float  pf0 = (float)s0 * div0;
        const float  pf1 = (float)s0 * div1;
        const double twopi  = 6.283185307179586;
        const double inv2pi = 0.15915494309189535;
        float th0 = (float)((double)pf0 - twopi * floor((double)pf0 * inv2pi));
        float th1 = (float)((double)pf1 - twopi * floor((double)pf1 * inv2pi));
        __sincosf(th0, &ps0, &pc0);
        __sincosf(th1, &ps1, &pc1);
    }
    // per-row rotation step
    float gs0, gc0, gs1, gc1;
    __sincosf(div0, &gs0, &gc0);
    __sincosf(div1, &gs1, &gc1);

    // packed temporal basis Tp[a] = (sin(a*div), cos(a*div)), a = 1..6
    u64 Tp0[7], Tp1[7];
    F2PACK(Tp0[1], gs0, gc0);
    F2PACK(Tp1[1], gs1, gc1);
    {
        float ts0 = gs0, tc0 = gc0, ts1 = gs1, tc1 = gc1;
#pragma unroll
        for (int a = 2; a <= 6; a++) {
            float ns0 = ts0 * gc0 + tc0 * gs0;
            float nc0 = tc0 * gc0 - ts0 * gs0;
            float ns1 = ts1 * gc1 + tc1 * gs1;
            float nc1 = tc1 * gc1 - ts1 * gs1;
            ts0 = ns0; tc0 = nc0; ts1 = ns1; tc1 = nc1;
            F2PACK(Tp0[a], ts0, tc0);
            F2PACK(Tp1[a], ts1, tc1);
        }
    }

    // packed pe state
    u64 pp0, pp1;
    F2PACK(pp0, ps0, pc0);
    F2PACK(pp1, ps1, pc1);

    float* __restrict__ outp = out + (size_t)s0 * D + f;
    const float* __restrict__ cvp = convS + jj * 512 + g0;   // +1536 per row

#pragma unroll
    for (int r = 0; r < RMAX; r++) {
        // 4x LDS.128 (warp-uniform broadcast): 8 packed pairs (md.y = pad, unused)
        const ulonglong2* __restrict__ mp2 = (const ulonglong2*)(mS + r * 16);
        const ulonglong2 ma = mp2[0], mb = mp2[1], mc = mp2[2], md = mp2[3];
        const ulonglong2 cv2 = *(const ulonglong2*)(cvp + r * 3 * 512);

        // seed: (0, m0) + (pe_sin, pe_cos)
        u64 t0, t1;
        F2ADD(t0, ma.x, pp0);
        F2ADD(t1, ma.x, pp1);
        F2FMA(t0, ma.y, Tp0[1], t0);  F2FMA(t1, ma.y, Tp1[1], t1);
        F2FMA(t0, mb.x, Tp0[2], t0);  F2FMA(t1, mb.x, Tp1[2], t1);
        F2FMA(t0, mb.y, Tp0[3], t0);  F2FMA(t1, mb.y, Tp1[3], t1);
        F2FMA(t0, mc.x, Tp0[4], t0);  F2FMA(t1, mc.x, Tp1[4], t1);
        F2FMA(t0, mc.y, Tp0[5], t0);  F2FMA(t1, mc.y, Tp1[5], t1);
        F2FMA(t0, md.x, Tp0[6], t0);  F2FMA(t1, md.x, Tp1[6], t1);

        ulonglong2 res;
        F2ADD(res.x, cv2.x, t0);
        F2ADD(res.y, cv2.y, t1);
        *(ulonglong2*)outp = res;

        // rotate pe (scalar chain), repack
        float ns0 = ps0 * gc0 + pc0 * gs0;
        float nc0 = pc0 * gc0 - ps0 * gs0;
        float ns1 = ps1 * gc1 + pc1 * gs1;
        float nc1 = pc1 * gc1 - ps1 * gs1;
        ps0 = ns0; pc0 = nc0; ps1 = ns1; pc1 = nc1;
        F2PACK(pp0, ps0, pc0);
        F2PACK(pp1, ps1, pc1);

        outp += D;
    }
}

// ---------------- single kernel: conv to smem, then tables-by-rotation ----------------
__global__ __launch_bounds__(NT, 3) void embed_kernel(
    const float* __restrict__ x,       // (4096, 7)
    const float* __restrict__ kern,    // (74, 8, 3)
    const int*   __restrict__ xm,      // (4096, 4)
    float*       __restrict__ out)     // (4096, 1536)
{
    extern __shared__ float smem[];
    float* __restrict__ convS = smem + SM_CONV;
    u64*   __restrict__ wcsD  = (u64*)(smem + SM_WCSD);
    float* __restrict__ sxA   = smem + SM_SXA;
    float* __restrict__ sxB   = smem + SM_SXB;
    float* __restrict__ mS    = smem + SM_M;

    // balanced partition: block b owns rows [b*SEQ/NBLK, (b+1)*SEQ/NBLK)  -> 9 or 10 rows
    const int b    = blockIdx.x;
    const int s0   = (b * SEQ) / NBLK;
    const int rmax = ((b + 1) * SEQ) / NBLK - s0;
    const int tid  = threadIdx.x;

    // ---- stage pre-duplicated weight pairs: wcsD[k][o] = (w, w), w = kern[o*24 + k*3 + 1]
    for (int e = tid; e < NUMK * KH; e += NT) {
        int o = e >> 3, k = e & 7;
        float w = kern[o * (KH * KW) + k * KW + 1];
        u64 wp; F2PACK(wp, w, w);
        wcsD[k * 76 + o] = wp;
    }
    // ---- stage x window (dual staggered copies): i in [0, WLEN), t = 3*s0 - 4 + i
    if (tid < CIN * WLEN) {
        int c = tid / WLEN, i = tid - c * WLEN;
        int t = 3 * s0 - 4 + i;
        float v = 0.0f;
        if (t >= 0 && t < TLEN) {
            int row = t / 3 + t % 3;
            if (row > SEQ - 1) row = SEQ - 1;
            v = x[row * CIN + c];
        }
        sxA[c * WPAD + i] = v;
        if (i > 0) sxB[c * WPAD + i - 1] = v;
    }
    // ---- stage duplicated temporal multiplicity pairs:
    //      mS[r][2a, 2a+1] = (a==0 ? 0 : m, m) where m = #{k : xm[s][k]==a}
    if (tid >= 288 && tid < 288 + SPER * 7) {
        int e = tid - 288;
        int r = e / 7, a = e - r * 7;
        int s = s0 + r; if (s > SEQ - 1) s = SEQ - 1;   // clamp (row beyond rmax unused)
        const int* xr = xm + s * 4;
        float m = (float)((xr[0] == a) + (xr[1] == a) + (xr[2] == a) + (xr[3] == a));
        mS[r * 16 + 2 * a]     = (a == 0) ? 0.0f : m;
        mS[r * 16 + 2 * a + 1] = m;
    }
    __syncthreads();

    if (rmax == SPER)
        compute_phases<SPER>(convS, wcsD, sxA, sxB, mS, s0, tid, out);
    else
        compute_phases<SPER - 1>(convS, wcsD, sxA, sxB, mS, s0, tid, out);
}

// ---------------- launch ----------------
extern "C" void kernel_launch(void* const* d_in, const int* in_sizes, int n_in,
                              void* d_out, int out_size)
{
    const float* x     = nullptr;
    const float* kern  = nullptr;
    const int*   xmark = nullptr;
    for (int i = 0; i < n_in; i++) {
        if      (in_sizes[i] == SEQ * CIN)        x     = (const float*)d_in[i];
        else if (in_sizes[i] == NUMK * KH * KW)   kern  = (const float*)d_in[i];
        else if (in_sizes[i] == SEQ * 4)          xmark = (const int*)d_in[i];
    }

    cudaFuncSetAttribute(embed_kernel,
                         cudaFuncAttributeMaxDynamicSharedMemorySize, SMEM_BYTES);

    embed_kernel<<<NBLK, NT, SMEM_BYTES>>>(x, kern, xmark, (float*)d_out);
}